// round 16
// baseline (speedup 1.0000x reference)
#include <cuda_runtime.h>
#include <cuda_bf16.h>
#include <cuda_fp16.h>
#include <math.h>
#include <stdint.h>

// Problem constants
#define BSZ   4
#define TLEN  1024
#define DDIM  1024
#define NH    16
#define DH    64
#define LPOS  128
#define NPOS  257            // 2*L+1
#define QPS   272            // padded stride for Qp rows

// -------- device scratch (no allocations allowed) --------
__device__ float g_Qp[BSZ*NH*TLEN*QPS];
__device__ float g_maskbias[BSZ*TLEN];         // 0 or -1e30
// input splits
__device__ __nv_bfloat16 g_XQhi[BSZ*TLEN*DDIM];
__device__ __nv_bfloat16 g_XQlo[BSZ*TLEN*DDIM];
__device__ __nv_bfloat16 g_XKhi[BSZ*TLEN*DDIM];
__device__ __nv_bfloat16 g_XKlo[BSZ*TLEN*DDIM];
__device__ __nv_bfloat16 g_XVhi[BSZ*TLEN*DDIM];
__device__ __nv_bfloat16 g_XVlo[BSZ*TLEN*DDIM];
// weight splits
__device__ __nv_bfloat16 g_WQhi[DDIM*DDIM];
__device__ __nv_bfloat16 g_WQlo[DDIM*DDIM];
__device__ __nv_bfloat16 g_WKhi[DDIM*DDIM];
__device__ __nv_bfloat16 g_WKlo[DDIM*DDIM];
__device__ __nv_bfloat16 g_WVhi[DDIM*DDIM];
__device__ __nv_bfloat16 g_WVlo[DDIM*DDIM];
__device__ __nv_bfloat16 g_WOhi[DDIM*DDIM];
__device__ __nv_bfloat16 g_WOlo[DDIM*DDIM];
// projection outputs (split; Q pre-scaled by 1/8; V stored as FP16 hi/lo bits)
__device__ __nv_bfloat16 g_Qhi[BSZ*TLEN*DDIM];
__device__ __nv_bfloat16 g_Qlo[BSZ*TLEN*DDIM];
__device__ __nv_bfloat16 g_Khi[BSZ*TLEN*DDIM];
__device__ __nv_bfloat16 g_Klo[BSZ*TLEN*DDIM];
__device__ __nv_bfloat16 g_Vhi[BSZ*TLEN*DDIM];   // fp16 bits
__device__ __nv_bfloat16 g_Vlo[BSZ*TLEN*DDIM];   // fp16 bits
// pos_emb bf16 hi/lo (padded to 264 rows, rows 257..263 zero)
__device__ __nv_bfloat16 g_Phi[264*DH];
__device__ __nv_bfloat16 g_Plo[264*DH];

// ============================================================
// small helpers
// ============================================================
__device__ __forceinline__ uint32_t pack_bf16(float lo, float hi) {
    uint32_t d;
    asm("cvt.rn.bf16x2.f32 %0, %1, %2;" : "=r"(d) : "f"(hi), "f"(lo));
    return d;
}
__device__ __forceinline__ float bf16lo_f(uint32_t u) { return __uint_as_float(u << 16); }
__device__ __forceinline__ float bf16hi_f(uint32_t u) { return __uint_as_float(u & 0xffff0000u); }

__device__ __forceinline__ uint32_t pack_f16(float lo, float hi) {
    __half2 h = __floats2half2_rn(lo, hi);
    return *(uint32_t*)&h;
}
__device__ __forceinline__ float f16lo_f(uint32_t u) {
    __half2 h = *(__half2*)&u; return __low2float(h);
}
__device__ __forceinline__ float f16hi_f(uint32_t u) {
    __half2 h = *(__half2*)&u; return __high2float(h);
}

// ============================================================
// mask_prep: normalize mask (int32-widened bool OR byte bool) -> float bias
// ============================================================
__global__ void mask_prep(const unsigned char* __restrict__ mraw)
{
    __shared__ int s_bytefmt;
    if (threadIdx.x == 0) s_bytefmt = 0;
    __syncthreads();

    int local = 0;
    for (int i = threadIdx.x; i < BSZ*TLEN; i += blockDim.x)
        if ((i & 3) != 0 && mraw[i] != 0) local = 1;
    if (local) atomicOr(&s_bytefmt, 1);
    __syncthreads();

    if (s_bytefmt) {
        for (int i = threadIdx.x; i < BSZ*TLEN; i += blockDim.x)
            g_maskbias[i] = mraw[i] ? -1e30f : 0.0f;
    } else {
        const int* mi = (const int*)mraw;
        for (int i = threadIdx.x; i < BSZ*TLEN; i += blockDim.x)
            g_maskbias[i] = mi[i] ? -1e30f : 0.0f;
    }
}

// ============================================================
// pos_prep: pos_emb fp32 -> bf16 hi/lo, zero-pad rows 257..263
// ============================================================
__global__ void pos_prep(const float* __restrict__ pos_emb)
{
    int i = blockIdx.x * blockDim.x + threadIdx.x;
    if (i >= 264*DH) return;
    float v = (i < NPOS*DH) ? pos_emb[i] : 0.0f;
    __nv_bfloat16 hv = __float2bfloat16(v);
    g_Phi[i] = hv;
    g_Plo[i] = __float2bfloat16(v - __bfloat162float(hv));
}

// ============================================================
// split_bf16: x(fp32) -> hi(bf16) + lo(bf16), vectorized by 4
// ============================================================
__global__ void __launch_bounds__(256) split_bf16(
    const float* __restrict__ x, __nv_bfloat16* __restrict__ hi,
    __nv_bfloat16* __restrict__ lo, int n4)
{
    int i = blockIdx.x * blockDim.x + threadIdx.x;
    if (i >= n4) return;
    float4 v = ((const float4*)x)[i];
    uint32_t h0 = pack_bf16(v.x, v.y);
    uint32_t h1 = pack_bf16(v.z, v.w);
    uint32_t l0 = pack_bf16(v.x - bf16lo_f(h0), v.y - bf16hi_f(h0));
    uint32_t l1 = pack_bf16(v.z - bf16lo_f(h1), v.w - bf16hi_f(h1));
    ((uint2*)hi)[i] = make_uint2(h0, h1);
    ((uint2*)lo)[i] = make_uint2(l0, l1);
}

// ============================================================
// mma.sync helpers (base sm_103 features)
// ============================================================
#define LDMX4(r0, r1, r2, r3, addr) \
    asm volatile("ldmatrix.sync.aligned.m8n8.x4.shared.b16 {%0,%1,%2,%3}, [%4];" \
        : "=r"(r0), "=r"(r1), "=r"(r2), "=r"(r3) : "r"(addr))

#define LDMX4T(r0, r1, r2, r3, addr) \
    asm volatile("ldmatrix.sync.aligned.m8n8.x4.trans.shared.b16 {%0,%1,%2,%3}, [%4];" \
        : "=r"(r0), "=r"(r1), "=r"(r2), "=r"(r3) : "r"(addr))

#define MMA16816(c, a, b) \
    asm volatile("mma.sync.aligned.m16n8k16.row.col.f32.bf16.bf16.f32 " \
        "{%0,%1,%2,%3}, {%4,%5,%6,%7}, {%8,%9}, {%0,%1,%2,%3};" \
        : "+f"((c)[0]), "+f"((c)[1]), "+f"((c)[2]), "+f"((c)[3]) \
        : "r"((a)[0]), "r"((a)[1]), "r"((a)[2]), "r"((a)[3]), \
          "r"((b)[0]), "r"((b)[1]))

#define MMAF16(c, a, b) \
    asm volatile("mma.sync.aligned.m16n8k16.row.col.f32.f16.f16.f32 " \
        "{%0,%1,%2,%3}, {%4,%5,%6,%7}, {%8,%9}, {%0,%1,%2,%3};" \
        : "+f"((c)[0]), "+f"((c)[1]), "+f"((c)[2]), "+f"((c)[3]) \
        : "r"((a)[0]), "r"((a)[1]), "r"((a)[2]), "r"((a)[3]), \
          "r"((b)[0]), "r"((b)[1]))

// ============================================================
// Tensor-core split-bf16 GEMM NT body (2-stage pipeline, 2 CTA/SM):
//   out = (Ahi+Alo)[M,K] * (Bhi+Blo)[N,K]^T   (hi*hi + hi*lo + lo*hi)
// F16OUT: write Chi/Clo as FP16 hi/lo bits (for V) instead of bf16.
// ============================================================
#define GEMM_BK      32
#define T_STRIDE     40
#define T_BYTES      (128*T_STRIDE*2)   // 10240
#define BUF_BYTES    (4*T_BYTES)        // 40960
#define GM_SMEM      (2*BUF_BYTES)      // 81920 -> 2 CTA/SM

__device__ __forceinline__ void gm_load_chunk(
    uint32_t sbuf,
    const __nv_bfloat16* __restrict__ Ahi, const __nv_bfloat16* __restrict__ Alo,
    const __nv_bfloat16* __restrict__ Bhi, const __nv_bfloat16* __restrict__ Blo,
    int m0, int n0, int k0, int tid)
{
#pragma unroll
    for (int j = 0; j < 8; j++) {
        int i = tid + j * 256;
        int t = i >> 9, idx = i & 511, row = idx >> 2, seg = idx & 3;
        uint32_t dst = sbuf + t * T_BYTES + row * (T_STRIDE*2) + seg * 16;
        const __nv_bfloat16* s = (t == 0) ? Ahi : (t == 1) ? Alo : (t == 2) ? Bhi : Blo;
        int gr = ((t < 2) ? m0 : n0) + row;
        const void* src = s + (size_t)gr * DDIM + k0 + seg * 8;
        asm volatile("cp.async.cg.shared.global [%0], [%1], 16;"
                     :: "r"(dst), "l"(src) : "memory");
    }
    asm volatile("cp.async.commit_group;" ::: "memory");
}

template <bool F16OUT>
__device__ __forceinline__ void gemm_body(
    const __nv_bfloat16* __restrict__ Ahi, const __nv_bfloat16* __restrict__ Alo,
    const __nv_bfloat16* __restrict__ Bhi, const __nv_bfloat16* __restrict__ Blo,
    float* __restrict__ C,
    __nv_bfloat16* __restrict__ Chi, __nv_bfloat16* __restrict__ Clo,
    float cscale)
{
    extern __shared__ __align__(128) char smc[];
    const uint32_t smb = (uint32_t)__cvta_generic_to_shared(smc);
    const int tid = threadIdx.x, lane = tid & 31, wid = tid >> 5;
    const int wm = wid & 3;
    const int warp_n = wid >> 2;
    const int m0 = blockIdx.y * 128, n0 = blockIdx.x * 128;

    float acc[2][8][4];
#pragma unroll
    for (int mi = 0; mi < 2; mi++)
#pragma unroll
        for (int ni = 0; ni < 8; ni++)
#pragma unroll
            for (int r = 0; r < 4; r++) acc[mi][ni][r] = 0.0f;

    const int sel = lane >> 3, rowl = lane & 7;
    const int arow = wm * 32 + rowl + (sel & 1) * 8;
    const int acol = (sel >> 1) * 8;
    const int brow = warp_n * 64 + rowl + (sel >> 1) * 8;
    const int bcol = (sel & 1) * 8;

    gm_load_chunk(smb, Ahi, Alo, Bhi, Blo, m0, n0, 0, tid);

    const int NCH = DDIM / GEMM_BK;   // 32
    for (int ch = 0; ch < NCH; ch++) {
        asm volatile("cp.async.wait_group 0;" ::: "memory");
        __syncthreads();
        if (ch + 1 < NCH)
            gm_load_chunk(smb + ((ch + 1) & 1) * BUF_BYTES,
                          Ahi, Alo, Bhi, Blo, m0, n0, (ch + 1) * GEMM_BK, tid);
        const uint32_t tb = smb + (ch & 1) * BUF_BYTES;
#pragma unroll
        for (int ks = 0; ks < 2; ks++) {
            uint32_t ah[2][4], al[2][4];
#pragma unroll
            for (int mi = 0; mi < 2; mi++) {
                uint32_t off = ((arow + mi * 16) * T_STRIDE + acol + ks * 16) * 2;
                LDMX4(ah[mi][0], ah[mi][1], ah[mi][2], ah[mi][3], tb + off);
                LDMX4(al[mi][0], al[mi][1], al[mi][2], al[mi][3], tb + T_BYTES + off);
            }
#pragma unroll
            for (int p = 0; p < 4; p++) {
                uint32_t off = ((brow + p * 16) * T_STRIDE + bcol + ks * 16) * 2;
                uint32_t bh0[2], bh1[2], bl0[2], bl1[2];
                LDMX4(bh0[0], bh0[1], bh1[0], bh1[1], tb + 2 * T_BYTES + off);
                LDMX4(bl0[0], bl0[1], bl1[0], bl1[1], tb + 3 * T_BYTES + off);
#pragma unroll
                for (int mi = 0; mi < 2; mi++) {
                    MMA16816(acc[mi][2*p],   ah[mi], bh0);
                    MMA16816(acc[mi][2*p],   ah[mi], bl0);
                    MMA16816(acc[mi][2*p],   al[mi], bh0);
                    MMA16816(acc[mi][2*p+1], ah[mi], bh1);
                    MMA16816(acc[mi][2*p+1], ah[mi], bl1);
                    MMA16816(acc[mi][2*p+1], al[mi], bh1);
                }
            }
        }
    }

    // epilogue: fp32 (optional) + hi/lo split (optional), scaled
    const int g = lane >> 2, t4 = lane & 3;
#pragma unroll
    for (int mi = 0; mi < 2; mi++) {
        const int r = m0 + wm * 32 + mi * 16 + g;
#pragma unroll
        for (int ni = 0; ni < 8; ni++) {
            const int col = n0 + warp_n * 64 + ni * 8 + t4 * 2;
            const size_t i0 = (size_t)r * DDIM + col;
            const size_t i1 = (size_t)(r + 8) * DDIM + col;
            float v0 = acc[mi][ni][0] * cscale, v1 = acc[mi][ni][1] * cscale;
            float v2 = acc[mi][ni][2] * cscale, v3 = acc[mi][ni][3] * cscale;
            if (C) {
                *(float2*)&C[i0] = make_float2(v0, v1);
                *(float2*)&C[i1] = make_float2(v2, v3);
            }
            if (Chi) {
                if (F16OUT) {
                    uint32_t h0 = pack_f16(v0, v1);
                    uint32_t h1 = pack_f16(v2, v3);
                    *(uint32_t*)(Chi + i0) = h0;
                    *(uint32_t*)(Chi + i1) = h1;
                    *(uint32_t*)(Clo + i0) =
                        pack_f16(v0 - f16lo_f(h0), v1 - f16hi_f(h0));
                    *(uint32_t*)(Clo + i1) =
                        pack_f16(v2 - f16lo_f(h1), v3 - f16hi_f(h1));
                } else {
                    uint32_t h0 = pack_bf16(v0, v1);
                    uint32_t h1 = pack_bf16(v2, v3);
                    *(uint32_t*)(Chi + i0) = h0;
                    *(uint32_t*)(Chi + i1) = h1;
                    *(uint32_t*)(Clo + i0) =
                        pack_bf16(v0 - bf16lo_f(h0), v1 - bf16hi_f(h0));
                    *(uint32_t*)(Clo + i1) =
                        pack_bf16(v2 - bf16lo_f(h1), v3 - bf16hi_f(h1));
                }
            }
        }
    }
}

// fused Q/K/V projection: blockIdx.z selects operands (uniform per CTA)
// Q pre-scaled by 1/8; V written as FP16 hi/lo.
__global__ void __launch_bounds__(256, 2) gemm_proj()
{
    if (blockIdx.z == 2) {
        gemm_body<true>(g_XVhi, g_XVlo, g_WVhi, g_WVlo,
                        nullptr, g_Vhi, g_Vlo, 1.0f);
    } else if (blockIdx.z == 0) {
        gemm_body<false>(g_XQhi, g_XQlo, g_WQhi, g_WQlo,
                         nullptr, g_Qhi, g_Qlo, 0.125f);
    } else {
        gemm_body<false>(g_XKhi, g_XKlo, g_WKhi, g_WKlo,
                         nullptr, g_Khi, g_Klo, 1.0f);
    }
}

// final output GEMM
__global__ void __launch_bounds__(256, 2) gemm_out(
    const __nv_bfloat16* __restrict__ Ahi, const __nv_bfloat16* __restrict__ Alo,
    float* __restrict__ C)
{
    gemm_body<false>(Ahi, Alo, g_WOhi, g_WOlo, C, nullptr, nullptr, 1.0f);
}

// ============================================================
// qp via mma.sync: Qp[bh][q][r] = Qscaled[bh,q,:] . pos_emb[r,:]
// CTA: one (b,h), 128 q rows. N padded 257->264. K=64.
// Pos hi/lo pre-split (pos_prep) and cp.async'd like Q.
// ============================================================
#define QPK_STR   72
#define QPK_QT_B  (128*QPK_STR*2)       // 18432
#define QPK_P_B   (264*QPK_STR*2)       // 38016
#define QPK_SMEM  (2*QPK_QT_B + 2*QPK_P_B)  // 112896

__global__ void __launch_bounds__(256, 2) qp_mma()
{
    extern __shared__ __align__(128) char smc[];
    const uint32_t smb = (uint32_t)__cvta_generic_to_shared(smc);
    const uint32_t QH = 0, QL = QPK_QT_B, PH = 2*QPK_QT_B, PL = 2*QPK_QT_B + QPK_P_B;
    const int tid = threadIdx.x, lane = tid & 31, w = tid >> 5;
    const int q0 = blockIdx.x * 128;
    const int bh = blockIdx.y;            // b*NH + h
    const int b = bh >> 4, h = bh & 15;
    const int bT = b * TLEN, hoff = h * DH;

    // stage Q hi/lo via cp.async
#pragma unroll
    for (int j = 0; j < 8; j++) {
        int i = tid + j * 256;
        int t = i >> 10, idx = i & 1023, row = idx >> 3, seg = idx & 7;
        uint32_t dst = smb + (t ? QL : QH) + row * (QPK_STR*2) + seg * 16;
        const __nv_bfloat16* s = t ? g_Qlo : g_Qhi;
        const void* src = s + (size_t)(bT + q0 + row) * DDIM + hoff + seg * 8;
        asm volatile("cp.async.cg.shared.global [%0], [%1], 16;"
                     :: "r"(dst), "l"(src) : "memory");
    }
    // stage pos hi/lo via cp.async (264 rows x 8 segs, 2 tiles)
    for (int i = tid; i < 2*264*8; i += 256) {
        int t = (i >= 264*8) ? 1 : 0;
        int idx = t ? i - 264*8 : i;
        int row = idx >> 3, seg = idx & 7;
        uint32_t dst = smb + (t ? PL : PH) + row * (QPK_STR*2) + seg * 16;
        const __nv_bfloat16* s = t ? g_Plo : g_Phi;
        const void* src = s + row * DH + seg * 8;
        asm volatile("cp.async.cg.shared.global [%0], [%1], 16;"
                     :: "r"(dst), "l"(src) : "memory");
    }
    asm volatile("cp.async.commit_group;" ::: "memory");
    asm volatile("cp.async.wait_group 0;" ::: "memory");
    __syncthreads();

    // A fragments (Q rows w*16..w*16+15, K=64)
    const int rowl = lane & 7, sel = lane >> 3;
    const int arow = rowl + (sel & 1) * 8, acol = (sel >> 1) * 8;
    uint32_t qh[4][4], ql[4][4];
#pragma unroll
    for (int j = 0; j < 4; j++) {
        uint32_t off = ((w * 16 + arow) * QPK_STR + acol + j * 16) * 2;
        LDMX4(qh[j][0], qh[j][1], qh[j][2], qh[j][3], smb + QH + off);
        LDMX4(ql[j][0], ql[j][1], ql[j][2], ql[j][3], smb + QL + off);
    }

    const int g = lane >> 2, t4 = lane & 3;
    const int qr0 = q0 + w * 16 + g;
    const size_t rb0 = ((size_t)bh * TLEN + qr0) * QPS;
    const size_t rb1 = rb0 + (size_t)8 * QPS;

    // 33 n-chunks of 8 r-values
    for (int nc = 0; nc < 33; nc++) {
        float acc[4] = {0.0f, 0.0f, 0.0f, 0.0f};
        uint32_t base = ((nc * 8 + rowl) * QPK_STR + sel * 8) * 2;
        uint32_t bh0[2], bh1[2], bh2[2], bh3[2];
        uint32_t bl0[2], bl1[2], bl2[2], bl3[2];
        LDMX4(bh0[0], bh0[1], bh1[0], bh1[1], smb + PH + base);
        LDMX4(bh2[0], bh2[1], bh3[0], bh3[1], smb + PH + base + 64);
        LDMX4(bl0[0], bl0[1], bl1[0], bl1[1], smb + PL + base);
        LDMX4(bl2[0], bl2[1], bl3[0], bl3[1], smb + PL + base + 64);
        MMA16816(acc, qh[0], bh0); MMA16816(acc, qh[0], bl0); MMA16816(acc, ql[0], bh0);
        MMA16816(acc, qh[1], bh1); MMA16816(acc, qh[1], bl1); MMA16816(acc, ql[1], bh1);
        MMA16816(acc, qh[2], bh2); MMA16816(acc, qh[2], bl2); MMA16816(acc, ql[2], bh2);
        MMA16816(acc, qh[3], bh3); MMA16816(acc, qh[3], bl3); MMA16816(acc, ql[3], bh3);
        int col = nc * 8 + t4 * 2;
        *(float2*)&g_Qp[rb0 + col] = make_float2(acc[0], acc[1]);
        *(float2*)&g_Qp[rb1 + col] = make_float2(acc[2], acc[3]);
    }
}

// ============================================================
// Tensor-core flash attention (3-stage KV pipeline, Q overlaid
// on buffer 2, 2 CTA/SM):
//  - S = Qh*Kh^T + Qh*Kl^T + Ql*Kh^T   (bf16, Q pre-scaled by 1/8)
//  - PV: single FP16 P x FP16 V hi/lo  (4 MMAs per j,dg-pair vs 6)
//  - epilogue writes bf16 hi/lo into the Wo-GEMM A-buffers
// ============================================================
#define KV_STRIDE 72
#define KV_TILE_B (64*KV_STRIDE*2)     // 9216 (144B rows: aligned)
#define KV_BUF    (4*KV_TILE_B)        // 36864
#define Q_TILE_B  (128*KV_STRIDE*2)    // 18432
#define ATQ_OFF   (2*KV_BUF)           // Q lives in buffer 2 initially
#define ATC_SMEM  (3*KV_BUF)           // 110592 -> 2 CTA/SM

__device__ __forceinline__ void at_load_kv(uint32_t sbuf,
    int bT, int hoff, int k0, int tid)
{
#pragma unroll
    for (int j = 0; j < 8; j++) {
        int i = tid + j * 256;
        int t = i >> 9, idx = i & 511, row = idx >> 3, seg = idx & 7;
        uint32_t dst = sbuf + t * KV_TILE_B + row * (KV_STRIDE*2) + seg * 16;
        const __nv_bfloat16* s = (t == 0) ? g_Khi : (t == 1) ? g_Klo
                               : (t == 2) ? g_Vhi : g_Vlo;
        const void* src = s + (size_t)(bT + k0 + row) * DDIM + hoff + seg * 8;
        asm volatile("cp.async.cg.shared.global [%0], [%1], 16;"
                     :: "r"(dst), "l"(src) : "memory");
    }
    asm volatile("cp.async.commit_group;" ::: "memory");
}

__global__ void __launch_bounds__(256, 2) attn_tc(
    __nv_bfloat16* __restrict__ Ohi, __nv_bfloat16* __restrict__ Olo)
{
    extern __shared__ __align__(128) char smc[];
    const uint32_t smb = (uint32_t)__cvta_generic_to_shared(smc);
    const int tid = threadIdx.x, lane = tid & 31, w = tid >> 5;
    const int qt = blockIdx.x & 7, h = (blockIdx.x >> 3) & 15, b = blockIdx.x >> 7;
    const int q0 = qt * 128, bT = b * TLEN, hoff = h * DH;

    const int rowl = lane & 7, sel = lane >> 3;
    const int arow = rowl + (sel & 1) * 8, acol = (sel >> 1) * 8;
    const int brow = rowl + (sel >> 1) * 8, bcol = (sel & 1) * 8;
    const int vrow = (sel & 1) * 8 + rowl, vcol = (sel >> 1) * 8;

    // stage Q hi/lo into buffer-2 region (group 0)
#pragma unroll
    for (int j = 0; j < 8; j++) {
        int i = tid + j * 256;
        int t = i >> 10, idx = i & 1023, row = idx >> 3, seg = idx & 7;
        uint32_t dst = smb + ATQ_OFF + t * Q_TILE_B + row * (KV_STRIDE*2) + seg * 16;
        const __nv_bfloat16* s = t ? g_Qlo : g_Qhi;
        const void* src = s + (size_t)(bT + q0 + row) * DDIM + hoff + seg * 8;
        asm volatile("cp.async.cg.shared.global [%0], [%1], 16;"
                     :: "r"(dst), "l"(src) : "memory");
    }
    asm volatile("cp.async.commit_group;" ::: "memory");
    // prefetch KV tiles 0,1 (groups 1,2)
    at_load_kv(smb,          bT, hoff, 0,  tid);
    at_load_kv(smb + KV_BUF, bT, hoff, 64, tid);

    // wait for Q (oldest group), register Q fragments, release buffer 2
    asm volatile("cp.async.wait_group 2;" ::: "memory");
    __syncthreads();
    uint32_t qh[4][4], ql[4][4];
#pragma unroll
    for (int j = 0; j < 4; j++) {
        uint32_t off = ATQ_OFF + ((w * 16 + arow) * KV_STRIDE + acol + j * 16) * 2;
        LDMX4(qh[j][0], qh[j][1], qh[j][2], qh[j][3], smb + off);
        LDMX4(ql[j][0], ql[j][1], ql[j][2], ql[j][3], smb + Q_TILE_B + off);
    }
    __syncthreads();   // all warps done reading Q; buffer 2 reusable

    float o[8][4];
#pragma unroll
    for (int ni = 0; ni < 8; ni++)
#pragma unroll
        for (int r = 0; r < 4; r++) o[ni][r] = 0.0f;
    float mrow0 = -1e30f, mrow1 = -1e30f, lrow0 = 0.0f, lrow1 = 0.0f;

    const int qr0 = q0 + w * 16 + (lane >> 2);
    const float* qpr0 = g_Qp + ((size_t)(b*NH + h)*TLEN + qr0) * QPS;
    const float* qpr1 = qpr0 + 8 * QPS;
    const float* mb = g_maskbias + bT;

    for (int kt = 0; kt < 16; kt++) {
        if (kt < 15)
            asm volatile("cp.async.wait_group 1;" ::: "memory");
        else
            asm volatile("cp.async.wait_group 0;" ::: "memory");
        __syncthreads();
        if (kt + 2 < 16)
            at_load_kv(smb + ((kt + 2) % 3) * KV_BUF, bT, hoff, (kt + 2) * 64, tid);
        const uint32_t vb = smb + (kt % 3) * KV_BUF;

        // ---- S = Q K^T (pre-scaled, bf16 3-term) ----
        float s[8][4];
#pragma unroll
        for (int ni = 0; ni < 8; ni++)
#pragma unroll
            for (int r = 0; r < 4; r++) s[ni][r] = 0.0f;
#pragma unroll
        for (int j = 0; j < 4; j++) {
#pragma unroll
            for (int p = 0; p < 4; p++) {
                uint32_t off = ((p * 16 + brow) * KV_STRIDE + bcol + j * 16) * 2;
                uint32_t h0, h1, h2, h3, l0, l1, l2, l3;
                LDMX4(h0, h1, h2, h3, vb + off);
                LDMX4(l0, l1, l2, l3, vb + KV_TILE_B + off);
                uint32_t bfh0[2] = {h0, h1}, bfh1[2] = {h2, h3};
                uint32_t bfl0[2] = {l0, l1}, bfl1[2] = {l2, l3};
                MMA16816(s[2*p],   qh[j], bfh0);
                MMA16816(s[2*p],   qh[j], bfl0);
                MMA16816(s[2*p],   ql[j], bfh0);
                MMA16816(s[2*p+1], qh[j], bfh1);
                MMA16816(s[2*p+1], qh[j], bfl1);
                MMA16816(s[2*p+1], ql[j], bfh1);
            }
        }

        // ---- pos gather (pre-scaled Qp) + mask bias ----
        const int kc0 = kt * 64 + (lane & 3) * 2;
#pragma unroll
        for (int ni = 0; ni < 8; ni++) {
            int kc = kc0 + ni * 8;
            float2 bias = *(const float2*)(mb + kc);
            int d0 = kc - qr0;
            int r00 = min(max(d0,     -LPOS), LPOS) + LPOS;
            int r01 = min(max(d0 + 1, -LPOS), LPOS) + LPOS;
            int r10 = min(max(d0 - 8, -LPOS), LPOS) + LPOS;
            int r11 = min(max(d0 - 7, -LPOS), LPOS) + LPOS;
            s[ni][0] = s[ni][0] + qpr0[r00] + bias.x;
            s[ni][1] = s[ni][1] + qpr0[r01] + bias.y;
            s[ni][2] = s[ni][2] + qpr1[r10] + bias.x;
            s[ni][3] = s[ni][3] + qpr1[r11] + bias.y;
        }

        // ---- online softmax (rows: qr0 and qr0+8) ----
        float mx0 = s[0][0], mx1 = s[0][2];
#pragma unroll
        for (int ni = 0; ni < 8; ni++) {
            mx0 = fmaxf(mx0, fmaxf(s[ni][0], s[ni][1]));
            mx1 = fmaxf(mx1, fmaxf(s[ni][2], s[ni][3]));
        }
        mx0 = fmaxf(mx0, __shfl_xor_sync(0xffffffffu, mx0, 1));
        mx0 = fmaxf(mx0, __shfl_xor_sync(0xffffffffu, mx0, 2));
        mx1 = fmaxf(mx1, __shfl_xor_sync(0xffffffffu, mx1, 1));
        mx1 = fmaxf(mx1, __shfl_xor_sync(0xffffffffu, mx1, 2));
        float mn0 = fmaxf(mrow0, mx0), mn1 = fmaxf(mrow1, mx1);
        float a0 = __expf(mrow0 - mn0), a1 = __expf(mrow1 - mn1);
        mrow0 = mn0; mrow1 = mn1;
        float sum0 = 0.0f, sum1 = 0.0f;
#pragma unroll
        for (int ni = 0; ni < 8; ni++) {
            s[ni][0] = __expf(s[ni][0] - mn0); sum0 += s[ni][0];
            s[ni][1] = __expf(s[ni][1] - mn0); sum0 += s[ni][1];
            s[ni][2] = __expf(s[ni][2] - mn1); sum1 += s[ni][2];
            s[ni][3] = __expf(s[ni][3] - mn1); sum1 += s[ni][3];
        }
        sum0 += __shfl_xor_sync(0xffffffffu, sum0, 1);
        sum0 += __shfl_xor_sync(0xffffffffu, sum0, 2);
        sum1 += __shfl_xor_sync(0xffffffffu, sum1, 1);
        sum1 += __shfl_xor_sync(0xffffffffu, sum1, 2);
        lrow0 = lrow0 * a0 + sum0;
        lrow1 = lrow1 * a1 + sum1;
#pragma unroll
        for (int ni = 0; ni < 8; ni++) {
            o[ni][0] *= a0; o[ni][1] *= a0;
            o[ni][2] *= a1; o[ni][3] *= a1;
        }

        // ---- O += P V  (single FP16 P x FP16 V hi/lo) ----
#pragma unroll
        for (int j = 0; j < 4; j++) {
            uint32_t ph[4];
            ph[0] = pack_f16(s[2*j][0],   s[2*j][1]);
            ph[1] = pack_f16(s[2*j][2],   s[2*j][3]);
            ph[2] = pack_f16(s[2*j+1][0], s[2*j+1][1]);
            ph[3] = pack_f16(s[2*j+1][2], s[2*j+1][3]);
#pragma unroll
            for (int dg = 0; dg < 4; dg++) {
                uint32_t off = ((j * 16 + vrow) * KV_STRIDE + dg * 16 + vcol) * 2;
                uint32_t vh0, vh1, vh2, vh3, vl0, vl1, vl2, vl3;
                LDMX4T(vh0, vh1, vh2, vh3, vb + 2 * KV_TILE_B + off);
                LDMX4T(vl0, vl1, vl2, vl3, vb + 3 * KV_TILE_B + off);
                uint32_t bh0[2] = {vh0, vh1}, bh1[2] = {vh2, vh3};
                uint32_t bl0[2] = {vl0, vl1}, bl1[2] = {vl2, vl3};
                MMAF16(o[2*dg],   ph, bh0);
                MMAF16(o[2*dg],   ph, bl0);
                MMAF16(o[2*dg+1], ph, bh1);
                MMAF16(o[2*dg+1], ph, bl1);
            }
        }
    }

    // ---- epilogue: normalize, split to bf16 hi/lo ----
    float inv0 = 1.0f / lrow0, inv1 = 1.0f / lrow1;
    const size_t obase0 = (size_t)(bT + qr0) * DDIM + hoff;
    const size_t obase1 = obase0 + (size_t)8 * DDIM;
#pragma unroll
    for (int ni = 0; ni < 8; ni++) {
        int dc = ni * 8 + (lane & 3) * 2;
        float f0 = o[ni][0] * inv0, f1 = o[ni][1] * inv0;
        float f2 = o[ni][2] * inv1, f3 = o[ni][3] * inv1;
        uint32_t h0 = pack_bf16(f0, f1);
        uint32_t h1 = pack_bf16(f2, f3);
        *(uint32_t*)(Ohi + obase0 + dc) = h0;
        *(uint32_t*)(Olo + obase0 + dc) = pack_bf16(f0 - bf16lo_f(h0), f1 - bf16hi_f(h0));
        *(uint32_t*)(Ohi + obase1 + dc) = h1;
        *(uint32_t*)(Olo + obase1 + dc) = pack_bf16(f2 - bf16lo_f(h1), f3 - bf16hi_f(h1));
    }
}

// ============================================================
// host launcher
// ============================================================
extern "C" void kernel_launch(void* const* d_in, const int* in_sizes, int n_in,
                              void* d_out, int out_size)
{
    const float* x_q = (const float*)d_in[0];
    const float* x_k = (const float*)d_in[1];
    const float* x_v = (const float*)d_in[2];
    const unsigned char* mask_raw = (const unsigned char*)d_in[3];
    const float* Wq = (const float*)d_in[4];
    const float* Wk = (const float*)d_in[5];
    const float* Wv = (const float*)d_in[6];
    const float* Wo = (const float*)d_in[7];
    const float* pos_emb = (const float*)d_in[8];
    float* out = (float*)d_out;

    void* p;
    __nv_bfloat16 *XQh, *XQl, *XKh, *XKl, *XVh, *XVl;
    __nv_bfloat16 *WQh, *WQl, *WKh, *WKl, *WVh, *WVl, *WOh, *WOl;
    cudaGetSymbolAddress(&p, g_XQhi); XQh = (__nv_bfloat16*)p;
    cudaGetSymbolAddress(&p, g_XQlo); XQl = (__nv_bfloat16*)p;
    cudaGetSymbolAddress(&p, g_XKhi); XKh = (__nv_bfloat16*)p;
    cudaGetSymbolAddress(&p, g_XKlo); XKl = (__nv_bfloat16*)p;
    cudaGetSymbolAddress(&p, g_XVhi); XVh = (__nv_bfloat16*)p;
    cudaGetSymbolAddress(&p, g_XVlo); XVl = (__nv_bfloat16*)p;
    cudaGetSymbolAddress(&p, g_WQhi); WQh = (__nv_bfloat16*)p;
    cudaGetSymbolAddress(&p, g_WQlo); WQl = (__nv_bfloat16*)p;
    cudaGetSymbolAddress(&p, g_WKhi); WKh = (__nv_bfloat16*)p;
    cudaGetSymbolAddress(&p, g_WKlo); WKl = (__nv_bfloat16*)p;
    cudaGetSymbolAddress(&p, g_WVhi); WVh = (__nv_bfloat16*)p;
    cudaGetSymbolAddress(&p, g_WVlo); WVl = (__nv_bfloat16*)p;
    cudaGetSymbolAddress(&p, g_WOhi); WOh = (__nv_bfloat16*)p;
    cudaGetSymbolAddress(&p, g_WOlo); WOl = (__nv_bfloat16*)p;

    cudaFuncSetAttribute(gemm_proj, cudaFuncAttributeMaxDynamicSharedMemorySize, GM_SMEM);
    cudaFuncSetAttribute(gemm_out,  cudaFuncAttributeMaxDynamicSharedMemorySize, GM_SMEM);
    cudaFuncSetAttribute(qp_mma,    cudaFuncAttributeMaxDynamicSharedMemorySize, QPK_SMEM);
    cudaFuncSetAttribute(attn_tc,   cudaFuncAttributeMaxDynamicSharedMemorySize, ATC_SMEM);

    const int n4A = (BSZ*TLEN*DDIM) / 4;
    const int n4W = (DDIM*DDIM) / 4;

    mask_prep<<<1, 256>>>(mask_raw);
    pos_prep<<<(264*DH + 255)/256, 256>>>(pos_emb);

    // all splits upfront
    split_bf16<<<n4A/256, 256>>>(x_q, XQh, XQl, n4A);
    split_bf16<<<n4A/256, 256>>>(x_k, XKh, XKl, n4A);
    split_bf16<<<n4A/256, 256>>>(x_v, XVh, XVl, n4A);
    split_bf16<<<n4W/256, 256>>>(Wq, WQh, WQl, n4W);
    split_bf16<<<n4W/256, 256>>>(Wk, WKh, WKl, n4W);
    split_bf16<<<n4W/256, 256>>>(Wv, WVh, WVl, n4W);
    split_bf16<<<n4W/256, 256>>>(Wo, WOh, WOl, n4W);

    // fused Q/K/V projections (Q pre-scaled by 1/8, V as fp16 hi/lo)
    gemm_proj<<<dim3(DDIM/128, (BSZ*TLEN)/128, 3), 256, GM_SMEM>>>();

    // Qp = Qscaled @ pos_emb^T via mma
    qp_mma<<<dim3(TLEN/128, BSZ*NH), 256, QPK_SMEM>>>();

    // attention -> writes hi/lo split into XQ buffers (reused as Wo-GEMM A)
    attn_tc<<<BSZ*NH*(TLEN/128), 256, ATC_SMEM>>>(XQh, XQl);

    // out = O @ Wo^T
    gemm_out<<<dim3(DDIM/128, (BSZ*TLEN)/128), 256, GM_SMEM>>>(XQh, XQl, out);
}